// round 2
// baseline (speedup 1.0000x reference)
#include <cuda_runtime.h>
#include <math.h>

#define NN 100000
#define NE 3200000
#define NB 256      // scan blocks
#define CHUNK 391   // ceil(NN/NB); NB*CHUNK = 100096 >= NN

// ---------------- device scratch (static, allocation-free) ----------------
__device__ int    g_is64;
__device__ int    g_deg[NN];
__device__ int    g_off[NN + 1];
__device__ int    g_cur[NN];
__device__ int    g_bsum[NB];
__device__ float  g_dis[NN];
__device__ float  g_sn[NN];
__device__ float2 g_edges[NE];      // .x = __int_as_float(src), .y = norm
__device__ float  g_ni[NN * 32];
__device__ float  g_h[NN * 32];
__device__ float  g_agg[NN * 32];

// ---------------- dtype detection ----------------
// edge_index is declared int64 in the reference, but JAX canonicalizes to
// int32 unless x64 is enabled. Detect layout from the data: int64 values in
// [0, 100000) have all-zero high words.
__global__ void k_detect(const unsigned int* __restrict__ w) {
    if (threadIdx.x == 0 && blockIdx.x == 0) {
        int is64 = 1;
        for (int i = 0; i < 64; i++)
            if (w[2 * i + 1] != 0u) { is64 = 0; break; }
        g_is64 = is64;
    }
}

__device__ __forceinline__ int load_idx(const void* ei, long long pos, int is64) {
    if (is64) return (int)((const long long*)ei)[pos];
    return ((const int*)ei)[pos];
}

// ---------------- graph preprocessing ----------------
__global__ void k_zero_deg() {
    int i = blockIdx.x * blockDim.x + threadIdx.x;
    if (i < NN) g_deg[i] = 0;
}

__global__ void k_deg(const void* __restrict__ ei) {
    int e = blockIdx.x * blockDim.x + threadIdx.x;
    if (e < NE) {
        int is64 = g_is64;
        int d = load_idx(ei, (long long)NE + e, is64);
        if ((unsigned)d < NN) atomicAdd(&g_deg[d], 1);
    }
}

__global__ void k_chunk_sum() {  // grid NB, block 512
    int b = blockIdx.x, t = threadIdx.x;
    int gi = b * CHUNK + t;
    int v = (t < CHUNK && gi < NN) ? g_deg[gi] : 0;
    #pragma unroll
    for (int o = 16; o; o >>= 1) v += __shfl_down_sync(0xffffffffu, v, o);
    __shared__ int ws[16];
    if ((t & 31) == 0) ws[t >> 5] = v;
    __syncthreads();
    if (t < 16) {
        int s = ws[t];
        #pragma unroll
        for (int o = 8; o; o >>= 1) s += __shfl_down_sync(0xffffu, s, o);
        if (t == 0) g_bsum[b] = s;
    }
}

__global__ void k_scan_bsum() {  // 1 thread
    int s = 0;
    for (int i = 0; i < NB; i++) { int v = g_bsum[i]; g_bsum[i] = s; s += v; }
    g_off[NN] = s;
}

__global__ void k_scan_chunk() {  // grid NB, block 512
    int b = blockIdx.x, t = threadIdx.x;
    int gi = b * CHUNK + t;
    int val = (t < CHUNK && gi < NN) ? g_deg[gi] : 0;
    int v = val;
    int lane = t & 31, wid = t >> 5;
    #pragma unroll
    for (int o = 1; o < 32; o <<= 1) {
        int n = __shfl_up_sync(0xffffffffu, v, o);
        if (lane >= o) v += n;
    }
    __shared__ int ws[16];
    if (lane == 31) ws[wid] = v;
    __syncthreads();
    if (t < 16) {
        int s = ws[t];
        #pragma unroll
        for (int o = 1; o < 16; o <<= 1) {
            int n = __shfl_up_sync(0xffffu, s, o);
            if (t >= o) s += n;
        }
        ws[t] = s;
    }
    __syncthreads();
    int base = g_bsum[b] + (wid ? ws[wid - 1] : 0);
    int excl = base + v - val;
    if (t < CHUNK && gi < NN) { g_off[gi] = excl; g_cur[gi] = excl; }
}

__global__ void k_dis() {
    int i = blockIdx.x * blockDim.x + threadIdx.x;
    if (i < NN) {
        float d = rsqrtf((float)(g_deg[i] + 1));
        g_dis[i] = d;
        g_sn[i]  = d * d;
    }
}

__global__ void k_build(const void* __restrict__ ei) {
    int e = blockIdx.x * blockDim.x + threadIdx.x;
    if (e < NE) {
        int is64 = g_is64;
        int s = load_idx(ei, e, is64);
        int d = load_idx(ei, (long long)NE + e, is64);
        if ((unsigned)s < NN && (unsigned)d < NN) {
            int p = atomicAdd(&g_cur[d], 1);
            g_edges[p] = make_float2(__int_as_float(s), g_dis[s] * g_dis[d]);
        }
    }
}

// ---------------- preprocessing MLP ----------------
__global__ void k_pre(const float* __restrict__ x,
                      const float* __restrict__ Wp, const float* __restrict__ bp,
                      const float* __restrict__ W1, const float* __restrict__ b1,
                      const float* __restrict__ W2, const float* __restrict__ b2) {
    __shared__ float sWp[60], sbp[10], sW1[320], sb1[32], sW2[320], sb2[32];
    int t = threadIdx.x;
    if (t < 60) sWp[t] = Wp[t];
    if (t < 10) sbp[t] = bp[t];
    for (int i = t; i < 320; i += 256) { sW1[i] = W1[i]; sW2[i] = W2[i]; }
    if (t < 32) { sb1[t] = b1[t]; sb2[t] = b2[t]; }
    __syncthreads();
    int i = blockIdx.x * blockDim.x + t;
    if (i >= NN) return;

    float xi[6];
    #pragma unroll
    for (int f = 0; f < 6; f++) xi[f] = x[(size_t)i * 6 + f];

    float h0[10];
    #pragma unroll
    for (int c = 0; c < 10; c++) {
        float s = sbp[c];
        #pragma unroll
        for (int f = 0; f < 6; f++) s += xi[f] * sWp[f * 10 + c];
        h0[c] = 1.0f / (1.0f + expf(-s));
    }

    float ni[32], hh[32];
    #pragma unroll
    for (int c = 0; c < 32; c++) { ni[c] = sb1[c]; hh[c] = sb2[c]; }
    #pragma unroll
    for (int k = 0; k < 10; k++) {
        float v = h0[k];
        const float4* w1 = (const float4*)(sW1 + k * 32);
        const float4* w2 = (const float4*)(sW2 + k * 32);
        #pragma unroll
        for (int q = 0; q < 8; q++) {
            float4 a = w1[q], b = w2[q];
            ni[4*q+0] += v * a.x; ni[4*q+1] += v * a.y; ni[4*q+2] += v * a.z; ni[4*q+3] += v * a.w;
            hh[4*q+0] += v * b.x; hh[4*q+1] += v * b.y; hh[4*q+2] += v * b.z; hh[4*q+3] += v * b.w;
        }
    }
    float4* np = (float4*)(g_ni + (size_t)i * 32);
    float4* hp = (float4*)(g_h  + (size_t)i * 32);
    #pragma unroll
    for (int q = 0; q < 8; q++) {
        np[q] = make_float4(fmaxf(ni[4*q],0.f), fmaxf(ni[4*q+1],0.f), fmaxf(ni[4*q+2],0.f), fmaxf(ni[4*q+3],0.f));
        hp[q] = make_float4(fmaxf(hh[4*q],0.f), fmaxf(hh[4*q+1],0.f), fmaxf(hh[4*q+2],0.f), fmaxf(hh[4*q+3],0.f));
    }
}

// ---------------- edge aggregation: warp per dst node ----------------
__global__ void k_agg() {
    int w    = (blockIdx.x * blockDim.x + threadIdx.x) >> 5;
    int lane = threadIdx.x & 31;
    if (w >= NN) return;
    int beg = g_off[w], end = g_off[w + 1];
    float acc = __ldg(&g_h[(size_t)w * 32 + lane]) * g_sn[w];
    float a0 = 0.f, a1 = 0.f, a2 = 0.f, a3 = 0.f;
    int k = beg;
    for (; k + 4 <= end; k += 4) {
        float2 e0 = g_edges[k], e1 = g_edges[k+1], e2 = g_edges[k+2], e3 = g_edges[k+3];
        a0 += e0.y * __ldg(&g_h[(size_t)__float_as_int(e0.x) * 32 + lane]);
        a1 += e1.y * __ldg(&g_h[(size_t)__float_as_int(e1.x) * 32 + lane]);
        a2 += e2.y * __ldg(&g_h[(size_t)__float_as_int(e2.x) * 32 + lane]);
        a3 += e3.y * __ldg(&g_h[(size_t)__float_as_int(e3.x) * 32 + lane]);
    }
    for (; k < end; k++) {
        float2 e = g_edges[k];
        a0 += e.y * __ldg(&g_h[(size_t)__float_as_int(e.x) * 32 + lane]);
    }
    g_agg[(size_t)w * 32 + lane] = acc + (a0 + a1) + (a2 + a3);
}

// ---------------- per-layer node kernel ----------------
template <bool FINAL>
__global__ void k_node(const float* __restrict__ Wg,  const float* __restrict__ bg,
                       const float* __restrict__ Wd,  const float* __restrict__ bd,
                       const float* __restrict__ Wf1, const float* __restrict__ bf1,
                       const float* __restrict__ Wf2, const float* __restrict__ bf2,
                       float* __restrict__ out) {
    __shared__ float sWg[1024], sbg[32], sWd[2048], sbd[32];
    __shared__ float sWf1[2048], sbf1[32], sWf2[64], sbf2[2];
    int t = threadIdx.x;
    for (int i = t; i < 1024; i += 256) sWg[i] = Wg[i];
    for (int i = t; i < 2048; i += 256) sWd[i] = Wd[i];
    if (t < 32) { sbg[t] = bg[t]; sbd[t] = bd[t]; }
    if (FINAL) {
        for (int i = t; i < 2048; i += 256) sWf1[i] = Wf1[i];
        if (t < 64) sWf2[t] = Wf2[t];
        if (t < 32) sbf1[t] = bf1[t];
        if (t < 2)  sbf2[t] = bf2[t];
    }
    __syncthreads();
    int i = blockIdx.x * blockDim.x + t;
    if (i >= NN) return;

    float ar[32];
    {
        const float4* ap = (const float4*)(g_agg + (size_t)i * 32);
        #pragma unroll
        for (int q = 0; q < 8; q++) {
            float4 v = ap[q];
            ar[4*q] = v.x; ar[4*q+1] = v.y; ar[4*q+2] = v.z; ar[4*q+3] = v.w;
        }
    }
    float a[32];
    #pragma unroll
    for (int c = 0; c < 32; c++) a[c] = sbg[c];
    #pragma unroll
    for (int k = 0; k < 32; k++) {
        float xv = ar[k];
        const float4* w = (const float4*)(sWg + k * 32);
        #pragma unroll
        for (int q = 0; q < 8; q++) {
            float4 wv = w[q];
            a[4*q] += xv*wv.x; a[4*q+1] += xv*wv.y; a[4*q+2] += xv*wv.z; a[4*q+3] += xv*wv.w;
        }
    }
    #pragma unroll
    for (int c = 0; c < 32; c++) a[c] = fmaxf(a[c], 0.0f);

    float nr[32];
    {
        const float4* np = (const float4*)(g_ni + (size_t)i * 32);
        #pragma unroll
        for (int q = 0; q < 8; q++) {
            float4 v = np[q];
            nr[4*q] = v.x; nr[4*q+1] = v.y; nr[4*q+2] = v.z; nr[4*q+3] = v.w;
        }
    }
    float tt[32];
    #pragma unroll
    for (int c = 0; c < 32; c++) tt[c] = sbd[c];
    #pragma unroll
    for (int k = 0; k < 32; k++) {
        float xv = nr[k];
        const float4* w = (const float4*)(sWd + k * 32);
        #pragma unroll
        for (int q = 0; q < 8; q++) {
            float4 wv = w[q];
            tt[4*q] += xv*wv.x; tt[4*q+1] += xv*wv.y; tt[4*q+2] += xv*wv.z; tt[4*q+3] += xv*wv.w;
        }
    }
    #pragma unroll
    for (int k = 0; k < 32; k++) {
        float xv = a[k];
        const float4* w = (const float4*)(sWd + (32 + k) * 32);
        #pragma unroll
        for (int q = 0; q < 8; q++) {
            float4 wv = w[q];
            tt[4*q] += xv*wv.x; tt[4*q+1] += xv*wv.y; tt[4*q+2] += xv*wv.z; tt[4*q+3] += xv*wv.w;
        }
    }
    #pragma unroll
    for (int c = 0; c < 32; c++) tt[c] = fmaxf(tt[c], 0.0f);

    if (!FINAL) {
        float4* hp = (float4*)(g_h + (size_t)i * 32);
        #pragma unroll
        for (int q = 0; q < 8; q++)
            hp[q] = make_float4(tt[4*q], tt[4*q+1], tt[4*q+2], tt[4*q+3]);
    } else {
        float z[32];
        #pragma unroll
        for (int c = 0; c < 32; c++) z[c] = sbf1[c];
        #pragma unroll
        for (int k = 0; k < 32; k++) {
            float xv = nr[k];
            const float4* w = (const float4*)(sWf1 + k * 32);
            #pragma unroll
            for (int q = 0; q < 8; q++) {
                float4 wv = w[q];
                z[4*q] += xv*wv.x; z[4*q+1] += xv*wv.y; z[4*q+2] += xv*wv.z; z[4*q+3] += xv*wv.w;
            }
        }
        #pragma unroll
        for (int k = 0; k < 32; k++) {
            float xv = tt[k];
            const float4* w = (const float4*)(sWf1 + (32 + k) * 32);
            #pragma unroll
            for (int q = 0; q < 8; q++) {
                float4 wv = w[q];
                z[4*q] += xv*wv.x; z[4*q+1] += xv*wv.y; z[4*q+2] += xv*wv.z; z[4*q+3] += xv*wv.w;
            }
        }
        float o0 = sbf2[0], o1 = sbf2[1];
        #pragma unroll
        for (int k = 0; k < 32; k++) {
            float zv = fmaxf(z[k], 0.0f);
            o0 += zv * sWf2[2*k + 0];
            o1 += zv * sWf2[2*k + 1];
        }
        ((float2*)out)[i] = make_float2(o0, o1);
    }
}

// ---------------- launch ----------------
extern "C" void kernel_launch(void* const* d_in, const int* in_sizes, int n_in,
                              void* d_out, int out_size) {
    const float* x  = (const float*)d_in[0];
    const void*  ei = d_in[1];
    const float* Wpre = (const float*)d_in[2];
    const float* bpre = (const float*)d_in[3];
    const float* Wfc1 = (const float*)d_in[4];
    const float* bfc1 = (const float*)d_in[5];
    const float* Wfc2 = (const float*)d_in[6];
    const float* bfc2 = (const float*)d_in[7];
    const float* Wgcn = (const float*)d_in[8];
    const float* bgcn = (const float*)d_in[9];
    const float* Wden = (const float*)d_in[10];
    const float* bden = (const float*)d_in[11];
    const float* Wf1  = (const float*)d_in[12];
    const float* bf1  = (const float*)d_in[13];
    const float* Wf2  = (const float*)d_in[14];
    const float* bf2  = (const float*)d_in[15];
    float* out = (float*)d_out;

    int nb = (NN + 255) / 256;
    int eb = (NE + 255) / 256;

    k_detect<<<1, 32>>>((const unsigned int*)ei);
    k_zero_deg<<<nb, 256>>>();
    k_deg<<<eb, 256>>>(ei);
    k_chunk_sum<<<NB, 512>>>();
    k_scan_bsum<<<1, 1>>>();
    k_scan_chunk<<<NB, 512>>>();
    k_dis<<<nb, 256>>>();
    k_build<<<eb, 256>>>(ei);

    k_pre<<<nb, 256>>>(x, Wpre, bpre, Wfc1, bfc1, Wfc2, bfc2);

    int ab = (NN * 32 + 255) / 256;
    for (int l = 0; l < 6; l++) {
        k_agg<<<ab, 256>>>();
        if (l < 5)
            k_node<false><<<nb, 256>>>(Wgcn, bgcn, Wden, bden, Wf1, bf1, Wf2, bf2, out);
        else
            k_node<true><<<nb, 256>>>(Wgcn, bgcn, Wden, bden, Wf1, bf1, Wf2, bf2, out);
    }
}